// round 2
// baseline (speedup 1.0000x reference)
#include <cuda_runtime.h>

#define BB 64
#define SS 512
#define HH 768
#define TT 4
#define TSTART 2
#define TSTOP 3

// output offsets (float32 elements)
#define OFF_ISQA_PRED 0
#define OFF_CRF       64
#define OFF_LOSS1     32832
#define OFF_LOSS2     32833
#define OFF_TAGS      32834
#define OFF_ISQA      65602

__device__ float g_feats[BB * SS * TT];
__device__ float g_cls[BB * 2];
__device__ float g_Z[BB];
__device__ float g_gold[BB];

// ---------------------------------------------------------------------------
// K1: feats[b][s][t] = dot(emb[b][s+1], crf_W[t]) + crf_b[t]
// 4 rows per warp, crf_W staged in shared memory, float4 loads.
// ---------------------------------------------------------------------------
__global__ void feats_kernel(const float* __restrict__ emb,
                             const float* __restrict__ crf_W,
                             const float* __restrict__ crf_b) {
    __shared__ float sW[TT * HH];
    __shared__ float sb[TT];
    for (int i = threadIdx.x; i < TT * HH; i += blockDim.x) sW[i] = crf_W[i];
    if (threadIdx.x < TT) sb[threadIdx.x] = crf_b[threadIdx.x];
    __syncthreads();

    int warp = (blockIdx.x * blockDim.x + threadIdx.x) >> 5;  // 0..8191
    int lane = threadIdx.x & 31;
    int r0 = warp * 4;

    float acc[4][4];
#pragma unroll
    for (int r = 0; r < 4; ++r)
#pragma unroll
        for (int t = 0; t < TT; ++t) acc[r][t] = 0.f;

    const float4* W4 = (const float4*)sW;
#pragma unroll
    for (int c = 0; c < 6; ++c) {
        int h4 = c * 32 + lane;  // float4 index within 192
        float4 w0 = W4[h4];
        float4 w1 = W4[192 + h4];
        float4 w2 = W4[384 + h4];
        float4 w3 = W4[576 + h4];
#pragma unroll
        for (int r = 0; r < 4; ++r) {
            int row = r0 + r;
            int b = row >> 9;
            int s = row & 511;
            const float4* e4 = (const float4*)(emb + (long)(b * 513 + s + 1) * HH);
            float4 e = e4[h4];
            acc[r][0] += e.x * w0.x + e.y * w0.y + e.z * w0.z + e.w * w0.w;
            acc[r][1] += e.x * w1.x + e.y * w1.y + e.z * w1.z + e.w * w1.w;
            acc[r][2] += e.x * w2.x + e.y * w2.y + e.z * w2.z + e.w * w2.w;
            acc[r][3] += e.x * w3.x + e.y * w3.y + e.z * w3.z + e.w * w3.w;
        }
    }
#pragma unroll
    for (int r = 0; r < 4; ++r)
#pragma unroll
        for (int t = 0; t < TT; ++t)
#pragma unroll
            for (int off = 16; off > 0; off >>= 1)
                acc[r][t] += __shfl_xor_sync(0xFFFFFFFFu, acc[r][t], off);

    if (lane == 0) {
#pragma unroll
        for (int r = 0; r < 4; ++r) {
            float4 o;
            o.x = acc[r][0] + sb[0];
            o.y = acc[r][1] + sb[1];
            o.z = acc[r][2] + sb[2];
            o.w = acc[r][3] + sb[3];
            ((float4*)g_feats)[r0 + r] = o;
        }
    }
}

// ---------------------------------------------------------------------------
// K2: CLS logits: g_cls[b][c] = dot(emb[b][0], fc2_W[c]) + fc2_b[c]
// one warp per batch element
// ---------------------------------------------------------------------------
__global__ void cls_kernel(const float* __restrict__ emb,
                           const float* __restrict__ fc2_W,
                           const float* __restrict__ fc2_b) {
    int b = blockIdx.x;
    int lane = threadIdx.x;
    const float4* e4 = (const float4*)(emb + (long)b * 513 * HH);
    const float4* wa = (const float4*)fc2_W;
    const float4* wb = (const float4*)(fc2_W + HH);
    float a0 = 0.f, a1 = 0.f;
#pragma unroll
    for (int i = lane; i < 192; i += 32) {
        float4 e = e4[i];
        float4 x = wa[i];
        float4 y = wb[i];
        a0 += e.x * x.x + e.y * x.y + e.z * x.z + e.w * x.w;
        a1 += e.x * y.x + e.y * y.y + e.z * y.z + e.w * y.w;
    }
#pragma unroll
    for (int off = 16; off > 0; off >>= 1) {
        a0 += __shfl_xor_sync(0xFFFFFFFFu, a0, off);
        a1 += __shfl_xor_sync(0xFFFFFFFFu, a1, off);
    }
    if (lane == 0) {
        g_cls[b * 2 + 0] = a0 + fc2_b[0];
        g_cls[b * 2 + 1] = a1 + fc2_b[1];
    }
}

// ---------------------------------------------------------------------------
// K3: per-batch CRF: log-partition Z, gold score, Viterbi path + backtrace,
//     tags copy. One warp per batch.
// ---------------------------------------------------------------------------
__global__ void crf_kernel(const int* __restrict__ labels,
                           const float* __restrict__ trans,
                           float* __restrict__ out) {
    int b = blockIdx.x;
    int lane = threadIdx.x;

    __shared__ float sf[SS * TT];       // feats for this batch (8 KB)
    __shared__ unsigned int bps[SS];    // packed backpointers, 4 bytes/step

    // cooperative load of feats into smem
    const float4* fg = (const float4*)(g_feats + (long)b * SS * TT);
    float4* sf4 = (float4*)sf;
    for (int i = lane; i < SS; i += 32) sf4[i] = fg[i];

    // transitions into registers (broadcast load, replicated per lane)
    float tr[16];
#pragma unroll
    for (int i = 0; i < 16; ++i) tr[i] = trans[i];
    __syncwarp();

    // ---- gold score + tags copy (all 32 lanes) ----
    float gold = 0.f;
    for (int s = lane; s < SS; s += 32) {
        int tg = labels[b * 513 + 1 + s];
        gold += sf[s * TT + tg];
        out[OFF_TAGS + b * SS + s] = (float)tg;
        if (s < SS - 1) {
            int tg2 = labels[b * 513 + 2 + s];
            gold += tr[tg * 4 + tg2];
        }
    }
#pragma unroll
    for (int off = 16; off > 0; off >>= 1)
        gold += __shfl_xor_sync(0xFFFFFFFFu, gold, off);
    if (lane == 0) {
        int t0 = labels[b * 513 + 1];
        int tl = labels[b * 513 + 512];
        g_gold[b] = gold + tr[TSTART * 4 + t0] + tr[tl * 4 + TSTOP];
    }

    // ---- forward scan: lanes 0-3, state j = lane ----
    if (lane < 4) {
        int j = lane;
        float trk0 = tr[0 * 4 + j];
        float trk1 = tr[1 * 4 + j];
        float trk2 = tr[2 * 4 + j];
        float trk3 = tr[3 * 4 + j];
        float alpha = sf[j] + tr[TSTART * 4 + j];
        float delta = alpha;

        for (int t = 1; t < SS; ++t) {
            float f = sf[t * TT + j];
            float a0 = __shfl_sync(0xFu, alpha, 0, 4);
            float a1 = __shfl_sync(0xFu, alpha, 1, 4);
            float a2 = __shfl_sync(0xFu, alpha, 2, 4);
            float a3 = __shfl_sync(0xFu, alpha, 3, 4);
            float d0 = __shfl_sync(0xFu, delta, 0, 4);
            float d1 = __shfl_sync(0xFu, delta, 1, 4);
            float d2 = __shfl_sync(0xFu, delta, 2, 4);
            float d3 = __shfl_sync(0xFu, delta, 3, 4);

            float sa0 = a0 + trk0, sa1 = a1 + trk1, sa2 = a2 + trk2, sa3 = a3 + trk3;
            float m = fmaxf(fmaxf(sa0, sa1), fmaxf(sa2, sa3));
            float p = __expf(sa0 - m) + __expf(sa1 - m) + __expf(sa2 - m) + __expf(sa3 - m);
            alpha = m + __logf(p) + f;

            float sd0 = d0 + trk0, sd1 = d1 + trk1, sd2 = d2 + trk2, sd3 = d3 + trk3;
            float md = sd0;
            int bp = 0;
            if (sd1 > md) { md = sd1; bp = 1; }
            if (sd2 > md) { md = sd2; bp = 2; }
            if (sd3 > md) { md = sd3; bp = 3; }
            delta = md + f;
            ((unsigned char*)bps)[t * 4 + j] = (unsigned char)bp;
        }
        __syncwarp(0xFu);

        // terminal scores
        float zj = alpha + tr[j * 4 + TSTOP];
        float dj = delta + tr[j * 4 + TSTOP];
        float z0 = __shfl_sync(0xFu, zj, 0, 4);
        float z1 = __shfl_sync(0xFu, zj, 1, 4);
        float z2 = __shfl_sync(0xFu, zj, 2, 4);
        float z3 = __shfl_sync(0xFu, zj, 3, 4);
        float e0 = __shfl_sync(0xFu, dj, 0, 4);
        float e1 = __shfl_sync(0xFu, dj, 1, 4);
        float e2 = __shfl_sync(0xFu, dj, 2, 4);
        float e3 = __shfl_sync(0xFu, dj, 3, 4);

        if (j == 0) {
            float m = fmaxf(fmaxf(z0, z1), fmaxf(z2, z3));
            g_Z[b] = m + __logf(__expf(z0 - m) + __expf(z1 - m) +
                                __expf(z2 - m) + __expf(z3 - m));

            float md = e0;
            int tag = 0;
            if (e1 > md) { md = e1; tag = 1; }
            if (e2 > md) { md = e2; tag = 2; }
            if (e3 > md) { md = e3; tag = 3; }

            out[OFF_CRF + b * SS + (SS - 1)] = (float)tag;
            for (int t = SS - 1; t >= 1; --t) {
                tag = (int)((bps[t] >> (8 * tag)) & 3u);
                out[OFF_CRF + b * SS + t - 1] = (float)tag;
            }
        }
    }
}

// ---------------------------------------------------------------------------
// K4: losses, isqa_pred, IsQA copy. Single block of 64 threads.
// ---------------------------------------------------------------------------
__global__ void final_kernel(const int* __restrict__ isqa,
                             float* __restrict__ out) {
    __shared__ float red1[BB];
    __shared__ float red2[BB];
    int t = threadIdx.x;  // 0..63
    float l0 = g_cls[t * 2 + 0];
    float l1 = g_cls[t * 2 + 1];
    int pred = (l1 > l0) ? 1 : 0;  // first-max semantics of jnp.argmax
    out[OFF_ISQA_PRED + t] = (float)pred;

    float m = fmaxf(l0, l1);
    float lse = m + __logf(__expf(l0 - m) + __expf(l1 - m));
    int y = isqa[t];
    float lp = (y ? l1 : l0) - lse;
    red1[t] = -lp;
    red2[t] = g_Z[t] - g_gold[t];
    out[OFF_ISQA + t] = (float)y;
    __syncthreads();
    if (t == 0) {
        float s1 = 0.f, s2 = 0.f;
        for (int i = 0; i < BB; ++i) { s1 += red1[i]; s2 += red2[i]; }
        out[OFF_LOSS1] = s1 / BB;
        out[OFF_LOSS2] = s2 / BB;
    }
}

// ---------------------------------------------------------------------------
extern "C" void kernel_launch(void* const* d_in, const int* in_sizes, int n_in,
                              void* d_out, int out_size) {
    const float* emb    = (const float*)d_in[0];
    const int*   labels = (const int*)d_in[1];
    const int*   isqa   = (const int*)d_in[2];
    const float* fc2_W  = (const float*)d_in[3];
    const float* fc2_b  = (const float*)d_in[4];
    const float* crf_W  = (const float*)d_in[5];
    const float* crf_b  = (const float*)d_in[6];
    const float* trans  = (const float*)d_in[7];
    float* out = (float*)d_out;

    feats_kernel<<<1024, 256>>>(emb, crf_W, crf_b);
    cls_kernel<<<BB, 32>>>(emb, fc2_W, fc2_b);
    crf_kernel<<<BB, 32>>>(labels, trans, out);
    final_kernel<<<1, BB>>>(isqa, out);
}

// round 3
// speedup vs baseline: 2.8065x; 2.8065x over previous
#include <cuda_runtime.h>

#define BB 64
#define SS 512
#define HH 768
#define TT 4
#define TSTART 2
#define TSTOP 3

// output offsets (float32 elements)
#define OFF_ISQA_PRED 0
#define OFF_CRF       64
#define OFF_LOSS1     32832
#define OFF_LOSS2     32833
#define OFF_TAGS      32834
#define OFF_ISQA      65602

#define NCH 16
#define CHL 32
#define SFSTRIDE 2052   // floats per batch of staged feats in V-block smem
#define BPSTRIDE 516    // words per batch for backpointers

__device__ float g_feats[BB * SS * TT];
__device__ float g_cls[BB * 2];
__device__ float g_Z[BB];
__device__ float g_gold[BB];

// ---------------------------------------------------------------------------
// K1: blocks 0..1023 : feats[b][s][t] = dot(emb[b][s+1], crf_W[t]) + crf_b[t]
//     blocks 1024..1031 : cls logits (one warp per batch)
// ---------------------------------------------------------------------------
__global__ void feats_cls_kernel(const float* __restrict__ emb,
                                 const float* __restrict__ crf_W,
                                 const float* __restrict__ crf_b,
                                 const float* __restrict__ fc2_W,
                                 const float* __restrict__ fc2_b) {
    if (blockIdx.x < 1024) {
        __shared__ float sW[TT * HH];
        __shared__ float sb[TT];
        for (int i = threadIdx.x; i < TT * HH; i += blockDim.x) sW[i] = crf_W[i];
        if (threadIdx.x < TT) sb[threadIdx.x] = crf_b[threadIdx.x];
        __syncthreads();

        int warp = (blockIdx.x * blockDim.x + threadIdx.x) >> 5;  // 0..8191
        int lane = threadIdx.x & 31;
        int r0 = warp * 4;

        float acc[4][4];
#pragma unroll
        for (int r = 0; r < 4; ++r)
#pragma unroll
            for (int t = 0; t < TT; ++t) acc[r][t] = 0.f;

        const float4* W4 = (const float4*)sW;
#pragma unroll
        for (int c = 0; c < 6; ++c) {
            int h4 = c * 32 + lane;
            float4 w0 = W4[h4];
            float4 w1 = W4[192 + h4];
            float4 w2 = W4[384 + h4];
            float4 w3 = W4[576 + h4];
#pragma unroll
            for (int r = 0; r < 4; ++r) {
                int row = r0 + r;
                int b = row >> 9;
                int s = row & 511;
                const float4* e4 = (const float4*)(emb + (long)(b * 513 + s + 1) * HH);
                float4 e = e4[h4];
                acc[r][0] += e.x * w0.x + e.y * w0.y + e.z * w0.z + e.w * w0.w;
                acc[r][1] += e.x * w1.x + e.y * w1.y + e.z * w1.z + e.w * w1.w;
                acc[r][2] += e.x * w2.x + e.y * w2.y + e.z * w2.z + e.w * w2.w;
                acc[r][3] += e.x * w3.x + e.y * w3.y + e.z * w3.z + e.w * w3.w;
            }
        }
#pragma unroll
        for (int r = 0; r < 4; ++r)
#pragma unroll
            for (int t = 0; t < TT; ++t)
#pragma unroll
                for (int off = 16; off > 0; off >>= 1)
                    acc[r][t] += __shfl_xor_sync(0xFFFFFFFFu, acc[r][t], off);

        if (lane == 0) {
#pragma unroll
            for (int r = 0; r < 4; ++r) {
                float4 o;
                o.x = acc[r][0] + sb[0];
                o.y = acc[r][1] + sb[1];
                o.z = acc[r][2] + sb[2];
                o.w = acc[r][3] + sb[3];
                ((float4*)g_feats)[r0 + r] = o;
            }
        }
    } else {
        int warp = threadIdx.x >> 5;
        int lane = threadIdx.x & 31;
        int b = (blockIdx.x - 1024) * 8 + warp;
        const float4* e4 = (const float4*)(emb + (long)b * 513 * HH);
        const float4* wa = (const float4*)fc2_W;
        const float4* wb = (const float4*)(fc2_W + HH);
        float a0 = 0.f, a1 = 0.f;
#pragma unroll
        for (int i = lane; i < 192; i += 32) {
            float4 e = e4[i];
            float4 x = wa[i];
            float4 y = wb[i];
            a0 += e.x * x.x + e.y * x.y + e.z * x.z + e.w * x.w;
            a1 += e.x * y.x + e.y * y.y + e.z * y.z + e.w * y.w;
        }
#pragma unroll
        for (int off = 16; off > 0; off >>= 1) {
            a0 += __shfl_xor_sync(0xFFFFFFFFu, a0, off);
            a1 += __shfl_xor_sync(0xFFFFFFFFu, a1, off);
        }
        if (lane == 0) {
            g_cls[b * 2 + 0] = a0 + fc2_b[0];
            g_cls[b * 2 + 1] = a1 + fc2_b[1];
        }
    }
}

// ---------------------------------------------------------------------------
// K2: 80 blocks x 128 threads.
//   blocks 0..63  : Z-block (one batch): exp-domain chunked log-partition
//                   + gold score + tags copy.
//   blocks 64..79 : V-block (4 batches): sequential Viterbi delta scan
//                   (op order identical to the round-1 passing kernel)
//                   + parallel map-composition backtrace.
// ---------------------------------------------------------------------------
__global__ void crf_kernel(const int* __restrict__ labels,
                           const float* __restrict__ trans,
                           float* __restrict__ out) {
    __shared__ __align__(16) unsigned char sm[43008];
    int tid = threadIdx.x;

    if (blockIdx.x < 64) {
        // ================= Z-block =================
        float* sf = (float*)sm;            // 2048 floats: feats (log-domain)
        float* ef = (float*)(sm + 8192);   // 2048 floats: exp(feats)
        float* Ml = (float*)(sm + 16384);  // 16 chunks * 16 floats
        float* gr = (float*)(sm + 17408);  // 2 partial gold sums
        int b = blockIdx.x;

        const float4* fg = (const float4*)(g_feats + (long)b * SS * TT);
        float4* sf4 = (float4*)sf;
        for (int i = tid; i < 512; i += 128) sf4[i] = fg[i];
        __syncthreads();
        for (int i = tid; i < 2048; i += 128) ef[i] = __expf(sf[i]);
        __syncthreads();

        if (tid < 61) {
            // tid==0: chunk 0 with real init (steps 1..31).
            // tid>=1: chunk c = 1+(tid-1)/4, basis k=(tid-1)&3, steps c*32..c*32+31.
            float eW[16];
#pragma unroll
            for (int i = 0; i < 16; ++i) eW[i] = __expf(trans[i]);

            int c, tbase;
            float A0, A1, A2, A3, base = 0.f;
            int k = 0;
            if (tid == 0) {
                c = 0; tbase = 0;
                A0 = ef[0] * eW[TSTART * 4 + 0];
                A1 = ef[1] * eW[TSTART * 4 + 1];
                A2 = ef[2] * eW[TSTART * 4 + 2];
                A3 = ef[3] * eW[TSTART * 4 + 3];
            } else {
                c = 1 + (tid - 1) / 4;
                k = (tid - 1) & 3;
                tbase = c * CHL;
                A0 = (k == 0) ? 1.f : 0.f;
                A1 = (k == 1) ? 1.f : 0.f;
                A2 = (k == 2) ? 1.f : 0.f;
                A3 = (k == 3) ? 1.f : 0.f;
            }
            const float4* ef4 = (const float4*)ef;
            for (int i = 0; i < CHL; ++i) {
                int t = tbase + i;
                if (!(tid == 0 && i == 0)) {
                    float4 e = ef4[t];
                    float n0 = (A0 * eW[0] + A1 * eW[4] + A2 * eW[8]  + A3 * eW[12]) * e.x;
                    float n1 = (A0 * eW[1] + A1 * eW[5] + A2 * eW[9]  + A3 * eW[13]) * e.y;
                    float n2 = (A0 * eW[2] + A1 * eW[6] + A2 * eW[10] + A3 * eW[14]) * e.z;
                    float n3 = (A0 * eW[3] + A1 * eW[7] + A2 * eW[11] + A3 * eW[15]) * e.w;
                    A0 = n0; A1 = n1; A2 = n2; A3 = n3;
                }
                if ((i & 7) == 7) {  // periodic rescale keeps fp32 range safe
                    float s = A0 + A1 + A2 + A3;
                    float inv = __fdividef(1.f, s);
                    base += __logf(s);
                    A0 *= inv; A1 *= inv; A2 *= inv; A3 *= inv;
                }
            }
            Ml[c * 16 + k * 4 + 0] = fmaxf(base + __logf(A0), -1e30f);
            Ml[c * 16 + k * 4 + 1] = fmaxf(base + __logf(A1), -1e30f);
            Ml[c * 16 + k * 4 + 2] = fmaxf(base + __logf(A2), -1e30f);
            Ml[c * 16 + k * 4 + 3] = fmaxf(base + __logf(A3), -1e30f);
        } else if (tid >= 64) {
            // gold score + tags copy (threads 64..127, two full warps)
            float gold = 0.f;
            for (int s = tid - 64; s < SS; s += 64) {
                int tg = labels[b * 513 + 1 + s];
                gold += sf[s * 4 + tg];
                out[OFF_TAGS + b * SS + s] = (float)tg;
                if (s < SS - 1) {
                    int tg2 = labels[b * 513 + 2 + s];
                    gold += trans[tg * 4 + tg2];
                }
            }
#pragma unroll
            for (int off = 16; off > 0; off >>= 1)
                gold += __shfl_xor_sync(0xFFFFFFFFu, gold, off);
            if ((tid & 31) == 0) gr[(tid - 64) >> 5] = gold;
        }
        __syncthreads();

        if (tid == 0) {
            // combine 15 chunk matrices in log-domain (LSE matvec)
            float v0 = Ml[0], v1 = Ml[1], v2 = Ml[2], v3 = Ml[3];
            for (int c = 1; c < NCH; ++c) {
                const float* M = Ml + c * 16;
                float n[4];
#pragma unroll
                for (int j = 0; j < 4; ++j) {
                    float s0 = v0 + M[0 * 4 + j];
                    float s1 = v1 + M[1 * 4 + j];
                    float s2 = v2 + M[2 * 4 + j];
                    float s3 = v3 + M[3 * 4 + j];
                    float m = fmaxf(fmaxf(s0, s1), fmaxf(s2, s3));
                    n[j] = m + __logf(__expf(s0 - m) + __expf(s1 - m) +
                                      __expf(s2 - m) + __expf(s3 - m));
                }
                v0 = n[0]; v1 = n[1]; v2 = n[2]; v3 = n[3];
            }
            float s0 = v0 + trans[0 * 4 + TSTOP];
            float s1 = v1 + trans[1 * 4 + TSTOP];
            float s2 = v2 + trans[2 * 4 + TSTOP];
            float s3 = v3 + trans[3 * 4 + TSTOP];
            float m = fmaxf(fmaxf(s0, s1), fmaxf(s2, s3));
            g_Z[b] = m + __logf(__expf(s0 - m) + __expf(s1 - m) +
                                __expf(s2 - m) + __expf(s3 - m));
        }
        if (tid == 64) {
            float gold = gr[0] + gr[1];
            int t0 = labels[b * 513 + 1];
            int tl = labels[b * 513 + 512];
            g_gold[b] = gold + trans[TSTART * 4 + t0] + trans[tl * 4 + TSTOP];
        }
    } else {
        // ================= V-block (4 batches) =================
        float* sf         = (float*)sm;                   // 4*2052 floats
        unsigned int* bps = (unsigned int*)(sm + 32832);  // 4*516 words
        unsigned int* Fc  = (unsigned int*)(sm + 41088);  // 64 chunk maps
        int* btag         = (int*)(sm + 41344);           // 64 boundary tags
        int* ltag         = (int*)(sm + 41600);           // 4 last tags

        int base_b = (blockIdx.x - 64) * 4;

        for (int bbl = 0; bbl < 4; ++bbl) {
            const float4* fg = (const float4*)(g_feats + (long)(base_b + bbl) * SS * TT);
            float4* d4 = (float4*)(sf + bbl * SFSTRIDE);
            for (int i = tid; i < 512; i += 128) d4[i] = fg[i];
        }
        __syncthreads();

        // sequential Viterbi scan: lanes 0..15, one 4-lane unit per batch.
        if (tid < 16) {
            int unit = tid >> 2;
            int j = tid & 3;
            int bb = base_b + unit;
            const unsigned MASK = 0x0000FFFFu;

            float trk0 = trans[0 * 4 + j];
            float trk1 = trans[1 * 4 + j];
            float trk2 = trans[2 * 4 + j];
            float trk3 = trans[3 * 4 + j];
            const float* sfb = sf + unit * SFSTRIDE;
            unsigned char* bpb = (unsigned char*)(bps + unit * BPSTRIDE);
            float delta = sfb[j] + trans[TSTART * 4 + j];

#pragma unroll 4
            for (int t = 1; t < SS; ++t) {
                float d0 = __shfl_sync(MASK, delta, 0, 4);
                float d1 = __shfl_sync(MASK, delta, 1, 4);
                float d2 = __shfl_sync(MASK, delta, 2, 4);
                float d3 = __shfl_sync(MASK, delta, 3, 4);
                float f = sfb[t * 4 + j];
                float sd0 = d0 + trk0, sd1 = d1 + trk1, sd2 = d2 + trk2, sd3 = d3 + trk3;
                float md = sd0;
                int bp = 0;
                if (sd1 > md) { md = sd1; bp = 1; }
                if (sd2 > md) { md = sd2; bp = 2; }
                if (sd3 > md) { md = sd3; bp = 3; }
                delta = md + f;
                bpb[t * 4 + j] = (unsigned char)bp;
            }
            float dj = delta + trans[j * 4 + TSTOP];
            float e0 = __shfl_sync(MASK, dj, 0, 4);
            float e1 = __shfl_sync(MASK, dj, 1, 4);
            float e2 = __shfl_sync(MASK, dj, 2, 4);
            float e3 = __shfl_sync(MASK, dj, 3, 4);
            if (j == 0) {
                float md = e0;
                int tg = 0;
                if (e1 > md) { md = e1; tg = 1; }
                if (e2 > md) { md = e2; tg = 2; }
                if (e3 > md) { md = e3; tg = 3; }
                ltag[unit] = tg;
                out[OFF_CRF + bb * SS + (SS - 1)] = (float)tg;
            }
        }
        __syncthreads();

        // ---- backtrace: parallel map composition (integer-exact) ----
        int bbl = tid >> 4;      // batch within block (tid<64)
        int c = tid & 15;        // chunk
        int tstart = (c == 0) ? 1 : (c * CHL);
        int tend = c * CHL + 31;
        const unsigned int* bp_b = bps + bbl * BPSTRIDE;

        if (tid < 64) {
            // Phase A: compose chunk maps. Nibble i of F = tag reached from i.
            unsigned F = 0x3210u;  // identity
            for (int t = tend; t >= tstart; --t) {
                unsigned g = __byte_perm(bp_b[t], 0u, F);
                F = (g & 3u) | ((g >> 4) & 0x30u) | ((g >> 8) & 0x300u) |
                    ((g >> 12) & 0x3000u);
            }
            Fc[bbl * 16 + c] = F;
        }
        __syncthreads();

        // Phase B: resolve chunk-boundary tags (one thread per batch)
        if (tid < 64 && (tid & 15) == 0) {
            int tg = ltag[bbl];
            btag[bbl * 16 + 15] = tg;
            for (int c2 = 15; c2 >= 1; --c2) {
                tg = (int)((Fc[bbl * 16 + c2] >> (4 * tg)) & 3u);
                btag[bbl * 16 + c2 - 1] = tg;
            }
        }
        __syncthreads();

        // Phase C: replay each chunk, writing the path
        if (tid < 64) {
            int bb = base_b + bbl;
            int tg = btag[bbl * 16 + c];
            for (int t = tend; t >= tstart; --t) {
                tg = (int)((bp_b[t] >> (8 * tg)) & 3u);
                out[OFF_CRF + bb * SS + t - 1] = (float)tg;
            }
        }
    }
}

// ---------------------------------------------------------------------------
// K3: losses, isqa_pred, IsQA copy. Single block of 64 threads.
// ---------------------------------------------------------------------------
__global__ void final_kernel(const int* __restrict__ isqa,
                             float* __restrict__ out) {
    __shared__ float red1[BB];
    __shared__ float red2[BB];
    int t = threadIdx.x;  // 0..63
    float l0 = g_cls[t * 2 + 0];
    float l1 = g_cls[t * 2 + 1];
    out[OFF_ISQA_PRED + t] = (float)((l1 > l0) ? 1 : 0);

    float m = fmaxf(l0, l1);
    float lse = m + __logf(__expf(l0 - m) + __expf(l1 - m));
    int y = isqa[t];
    float lp = ((y != 0) ? l1 : l0) - lse;
    red1[t] = -lp;
    red2[t] = g_Z[t] - g_gold[t];
    out[OFF_ISQA + t] = (float)y;
    __syncthreads();
    if (t == 0) {
        float s1 = 0.f, s2 = 0.f;
        for (int i = 0; i < BB; ++i) { s1 += red1[i]; s2 += red2[i]; }
        out[OFF_LOSS1] = s1 / BB;
        out[OFF_LOSS2] = s2 / BB;
    }
}

// ---------------------------------------------------------------------------
extern "C" void kernel_launch(void* const* d_in, const int* in_sizes, int n_in,
                              void* d_out, int out_size) {
    const float* emb    = (const float*)d_in[0];
    const int*   labels = (const int*)d_in[1];
    const int*   isqa   = (const int*)d_in[2];
    const float* fc2_W  = (const float*)d_in[3];
    const float* fc2_b  = (const float*)d_in[4];
    const float* crf_W  = (const float*)d_in[5];
    const float* crf_b  = (const float*)d_in[6];
    const float* trans  = (const float*)d_in[7];
    float* out = (float*)d_out;

    feats_cls_kernel<<<1032, 256>>>(emb, crf_W, crf_b, fc2_W, fc2_b);
    crf_kernel<<<80, 128>>>(labels, trans, out);
    final_kernel<<<1, BB>>>(isqa, out);
}